// round 3
// baseline (speedup 1.0000x reference)
#include <cuda_runtime.h>
#include <float.h>
#include <math.h>
#include <stdint.h>

#define N   4096
#define D   256
#define B   4
#define K   20
#define TPB 256
#define VPT (N / TPB)   // 16 values per thread

// Scratch between the two stages (no cudaMalloc allowed).
__device__ float g_w[N * K];
__device__ int   g_idx[N * K];

// Order-preserving float -> uint32 (total order; bigger float => bigger uint).
__device__ __forceinline__ uint32_t f2ord(float f) {
    uint32_t u = __float_as_uint(f);
    return (u & 0x80000000u) ? ~u : (u | 0x80000000u);
}
__device__ __forceinline__ float ord2f(uint32_t u) {
    uint32_t v = (u & 0x80000000u) ? (u & 0x7fffffffu) : ~u;
    return __uint_as_float(v);
}

// Pack (value, column): high 32 = ordered value, low 32 = ~col.
// max of packed => max value, ties broken toward SMALLEST column (jax top_k order).
__device__ __forceinline__ uint64_t packvc(float v, int c) {
    return ((uint64_t)f2ord(v) << 32) | (uint32_t)(~c);
}

// ---------------------------------------------------------------------------
// Stage 1: per-row softmax stats + iterative top-20 of the logits.
// One 256-thread block per row; each thread holds 16 logits in registers.
// NO dynamic indexing of v[] anywhere (keeps it in registers).
// ---------------------------------------------------------------------------
__global__ __launch_bounds__(TPB) void topk_softmax_kernel(const float* __restrict__ M) {
    const int row  = blockIdx.x;
    const int tid  = threadIdx.x;
    const int lane = tid & 31;
    const int warp = tid >> 5;

    const float* r = M + (size_t)row * N;
    float v[VPT];
#pragma unroll
    for (int j = 0; j < VPT; j++) v[j] = r[tid + j * TPB];   // coalesced

    __shared__ float    sredf[8];
    __shared__ uint64_t sred64[8];
    __shared__ float    s_m, s_s;
    __shared__ uint64_t s_best;

    // ---- row max ----
    float m = -FLT_MAX;
#pragma unroll
    for (int j = 0; j < VPT; j++) m = fmaxf(m, v[j]);
#pragma unroll
    for (int off = 16; off; off >>= 1) m = fmaxf(m, __shfl_xor_sync(0xffffffffu, m, off));
    if (lane == 0) sredf[warp] = m;
    __syncthreads();
    if (warp == 0) {
        float mm = (lane < 8) ? sredf[lane] : -FLT_MAX;
#pragma unroll
        for (int off = 4; off; off >>= 1) mm = fmaxf(mm, __shfl_xor_sync(0xffffffffu, mm, off));
        if (lane == 0) s_m = mm;
    }
    __syncthreads();
    m = s_m;

    // ---- sum of exp ----
    float s = 0.f;
#pragma unroll
    for (int j = 0; j < VPT; j++) s += __expf(v[j] - m);
#pragma unroll
    for (int off = 16; off; off >>= 1) s += __shfl_xor_sync(0xffffffffu, s, off);
    if (lane == 0) sredf[warp] = s;
    __syncthreads();
    if (warp == 0) {
        float ss = (lane < 8) ? sredf[lane] : 0.f;
#pragma unroll
        for (int off = 4; off; off >>= 1) ss += __shfl_xor_sync(0xffffffffu, ss, off);
        if (lane == 0) s_s = ss;
    }
    __syncthreads();
    const float inv_s = 1.0f / s_s;

    // ---- iterative top-K argmax via packed (value, ~col) max ----
    for (int k = 0; k < K; k++) {
        // per-thread best (branch-free max chain over registers)
        uint64_t best = packvc(v[0], tid);
#pragma unroll
        for (int j = 1; j < VPT; j++) {
            uint64_t cand = packvc(v[j], tid + j * TPB);
            best = (cand > best) ? cand : best;
        }
        // warp reduce
#pragma unroll
        for (int off = 16; off; off >>= 1) {
            uint64_t o = __shfl_xor_sync(0xffffffffu, best, off);
            best = (o > best) ? o : best;
        }
        if (lane == 0) sred64[warp] = best;
        __syncthreads();
        if (warp == 0) {
            uint64_t bb = (lane < 8) ? sred64[lane] : 0ull;
#pragma unroll
            for (int off = 4; off; off >>= 1) {
                uint64_t o = __shfl_xor_sync(0xffffffffu, bb, off);
                bb = (o > bb) ? o : bb;
            }
            if (lane == 0) {
                s_best = bb;
                int   c  = (int)(~((uint32_t)bb));
                float fv = ord2f((uint32_t)(bb >> 32));
                g_idx[row * K + k] = c;
                g_w[row * K + k]   = __expf(fv - m) * inv_s;
            }
        }
        __syncthreads();
        const int c = (int)(~((uint32_t)s_best));
        // winner removal with STATIC indices only (v[] stays in registers)
#pragma unroll
        for (int j = 0; j < VPT; j++)
            if (c == tid + j * TPB) v[j] = -FLT_MAX;
    }
}

// ---------------------------------------------------------------------------
// Stage 2: out[b,i,:] = src1[b,i,:] + sum_k w[i,k] * src2[b, idx[i,k], :]
// One block per row i; 256 threads = (b in 0..3) x (64 float4 lanes of D=256).
// K loop fully unrolled -> ~20 outstanding LDG.128 per thread (L2-resident).
// ---------------------------------------------------------------------------
__global__ __launch_bounds__(256) void gather_wsum_kernel(const float* __restrict__ src1,
                                                          const float* __restrict__ src2,
                                                          float* __restrict__ out) {
    const int i   = blockIdx.x;
    const int tid = threadIdx.x;
    const int b   = tid >> 6;    // 0..3
    const int d4  = tid & 63;    // float4 lane

    __shared__ float sw[K];
    __shared__ int   sj[K];
    if (tid < K) { sw[tid] = g_w[i * K + tid]; sj[tid] = g_idx[i * K + tid]; }
    __syncthreads();

    const size_t base = ((size_t)b * N + i) * D;
    float4 acc = ((const float4*)(src1 + base))[d4];
    const float4* s2 = (const float4*)(src2 + (size_t)b * N * D);

#pragma unroll
    for (int k = 0; k < K; k++) {
        const float  w = sw[k];
        const float4 x = s2[(size_t)sj[k] * (D / 4) + d4];
        acc.x = fmaf(w, x.x, acc.x);
        acc.y = fmaf(w, x.y, acc.y);
        acc.z = fmaf(w, x.z, acc.z);
        acc.w = fmaf(w, x.w, acc.w);
    }
    ((float4*)(out + base))[d4] = acc;
}

// ---------------------------------------------------------------------------
extern "C" void kernel_launch(void* const* d_in, const int* in_sizes, int n_in,
                              void* d_out, int out_size) {
    const float* src1 = (const float*)d_in[0];
    const float* src2 = (const float*)d_in[1];
    const float* M    = (const float*)d_in[2];
    float*       out  = (float*)d_out;

    topk_softmax_kernel<<<N, TPB>>>(M);
    gather_wsum_kernel<<<N, 256>>>(src1, src2, out);
}

// round 4
// speedup vs baseline: 1.0867x; 1.0867x over previous
#include <cuda_runtime.h>
#include <float.h>
#include <math.h>
#include <stdint.h>

#define N   4096
#define D   256
#define B   4
#define K   20
#define TPB 256
#define NW  8              // warps per block
#define WCOLS (N / NW)     // 512 columns per warp
#define VPW  (WCOLS / 32)  // 16 values per thread

// Scratch between the two stages (no cudaMalloc allowed).
__device__ float g_w[N * K];
__device__ int   g_idx[N * K];

// Order-preserving float -> uint32 (total order; bigger float => bigger uint).
__device__ __forceinline__ uint32_t f2ord(float f) {
    uint32_t u = __float_as_uint(f);
    return (u & 0x80000000u) ? ~u : (u | 0x80000000u);
}
__device__ __forceinline__ float ord2f(uint32_t u) {
    uint32_t v = (u & 0x80000000u) ? (u & 0x7fffffffu) : ~u;
    return __uint_as_float(v);
}
// Pack (value, column): high 32 = ordered value, low 32 = ~col.
// max of packed => max value, ties broken toward SMALLEST column (jax order).
__device__ __forceinline__ uint64_t packvc(float v, int c) {
    return ((uint64_t)f2ord(v) << 32) | (uint32_t)(~c);
}

__device__ __forceinline__ uint64_t warp_max_u64(uint64_t x) {
#pragma unroll
    for (int off = 16; off; off >>= 1) {
        uint64_t o = __shfl_xor_sync(0xffffffffu, x, off);
        x = (o > x) ? o : x;
    }
    return x;
}

// ---------------------------------------------------------------------------
// Stage 1: softmax stats + top-20, hierarchical, barrier-free hot loop.
// 8 warps/block; warp w owns columns [w*512, (w+1)*512). ONE __syncthreads.
// ---------------------------------------------------------------------------
__global__ __launch_bounds__(TPB) void topk_softmax_kernel(const float* __restrict__ M) {
    const int row  = blockIdx.x;
    const int tid  = threadIdx.x;
    const int lane = tid & 31;
    const int warp = tid >> 5;

    const float* r = M + (size_t)row * N + warp * WCOLS;

    float v[VPW];
#pragma unroll
    for (int j = 0; j < VPW; j++) v[j] = r[lane + j * 32];   // 128B coalesced per warp

    __shared__ uint64_t s_cand[NW * K];
    __shared__ float    s_mw[NW];
    __shared__ float    s_sw[NW];

    // ---- per-warp max ----
    float mw = v[0];
#pragma unroll
    for (int j = 1; j < VPW; j++) mw = fmaxf(mw, v[j]);
#pragma unroll
    for (int off = 16; off; off >>= 1) mw = fmaxf(mw, __shfl_xor_sync(0xffffffffu, mw, off));

    // ---- per-warp sum of exp (rescaled later) ----
    float sw = 0.f;
#pragma unroll
    for (int j = 0; j < VPW; j++) sw += __expf(v[j] - mw);
#pragma unroll
    for (int off = 16; off; off >>= 1) sw += __shfl_xor_sync(0xffffffffu, sw, off);

    if (lane == 0) { s_mw[warp] = mw; s_sw[warp] = sw; }

    // ---- per-warp top-20 (warp-scoped rounds, no barriers) ----
    const int cbase = warp * WCOLS;
#pragma unroll 1
    for (int k = 0; k < K; k++) {
        uint64_t best = packvc(v[0], cbase + lane);
#pragma unroll
        for (int j = 1; j < VPW; j++) {
            uint64_t cand = packvc(v[j], cbase + lane + j * 32);
            best = (cand > best) ? cand : best;
        }
        best = warp_max_u64(best);
        if (lane == 0) s_cand[warp * K + k] = best;
        // remove winner (static indices only: v[] stays in registers)
        const int c = (int)(~((uint32_t)best)) - cbase;   // 0..511 within this warp
#pragma unroll
        for (int j = 0; j < VPW; j++)
            if (c == lane + j * 32) v[j] = -FLT_MAX;
    }

    __syncthreads();   // the ONLY block barrier

    // ---- warp 0 merges 8x20 candidates and emits weights ----
    if (warp == 0) {
        // row max + rescaled sum of exp
        float m = (lane < NW) ? s_mw[lane] : -FLT_MAX;
#pragma unroll
        for (int off = 4; off; off >>= 1) m = fmaxf(m, __shfl_xor_sync(0xffffffffu, m, off));
        float s = (lane < NW) ? s_sw[lane] * __expf(s_mw[lane] - m) : 0.f;
#pragma unroll
        for (int off = 4; off; off >>= 1) s += __shfl_xor_sync(0xffffffffu, s, off);
        const float inv_s = 1.0f / s;

        // 160 candidates -> 5 per lane
        uint64_t c0 = s_cand[lane];
        uint64_t c1 = s_cand[lane + 32];
        uint64_t c2 = s_cand[lane + 64];
        uint64_t c3 = s_cand[lane + 96];
        uint64_t c4 = s_cand[lane + 128];

#pragma unroll 1
        for (int k = 0; k < K; k++) {
            uint64_t best = c0;
            best = (c1 > best) ? c1 : best;
            best = (c2 > best) ? c2 : best;
            best = (c3 > best) ? c3 : best;
            best = (c4 > best) ? c4 : best;
            best = warp_max_u64(best);
            if (lane == 0) {
                int   c  = (int)(~((uint32_t)best));
                float fv = ord2f((uint32_t)(best >> 32));
                g_idx[row * K + k] = c;
                g_w[row * K + k]   = __expf(fv - m) * inv_s;
            }
            // clear winner wherever it lives
            if (c0 == best) c0 = 0;
            if (c1 == best) c1 = 0;
            if (c2 == best) c2 = 0;
            if (c3 == best) c3 = 0;
            if (c4 == best) c4 = 0;
        }
    }
}

// ---------------------------------------------------------------------------
// Stage 2: out[b,i,:] = src1[b,i,:] + sum_k w[i,k] * src2[b, idx[i,k], :]
// One block per row i; 256 threads = (b in 0..3) x (64 float4 lanes of D=256).
// ---------------------------------------------------------------------------
__global__ __launch_bounds__(256) void gather_wsum_kernel(const float* __restrict__ src1,
                                                          const float* __restrict__ src2,
                                                          float* __restrict__ out) {
    const int i   = blockIdx.x;
    const int tid = threadIdx.x;
    const int b   = tid >> 6;    // 0..3
    const int d4  = tid & 63;    // float4 lane

    __shared__ float sw[K];
    __shared__ int   sj[K];
    if (tid < K) { sw[tid] = g_w[i * K + tid]; sj[tid] = g_idx[i * K + tid]; }
    __syncthreads();

    const size_t base = ((size_t)b * N + i) * D;
    float4 acc = ((const float4*)(src1 + base))[d4];
    const float4* s2 = (const float4*)(src2 + (size_t)b * N * D);

#pragma unroll
    for (int k = 0; k < K; k++) {
        const float  w = sw[k];
        const float4 x = s2[(size_t)sj[k] * (D / 4) + d4];
        acc.x = fmaf(w, x.x, acc.x);
        acc.y = fmaf(w, x.y, acc.y);
        acc.z = fmaf(w, x.z, acc.z);
        acc.w = fmaf(w, x.w, acc.w);
    }
    ((float4*)(out + base))[d4] = acc;
}

// ---------------------------------------------------------------------------
extern "C" void kernel_launch(void* const* d_in, const int* in_sizes, int n_in,
                              void* d_out, int out_size) {
    const float* src1 = (const float*)d_in[0];
    const float* src2 = (const float*)d_in[1];
    const float* M    = (const float*)d_in[2];
    float*       out  = (float*)d_out;

    topk_softmax_kernel<<<N, TPB>>>(M);
    gather_wsum_kernel<<<N, 256>>>(src1, src2, out);
}

// round 5
// speedup vs baseline: 4.2848x; 3.9430x over previous
#include <cuda_runtime.h>
#include <float.h>
#include <math.h>
#include <stdint.h>

#define N    4096
#define D    256
#define K    20
#define TPB  256
#define NW   8              // warps per block
#define WCOLS 512           // columns per warp
#define VPW  16             // values per thread
#define RW   3              // per-warp candidate rounds
#define NCAND (NW * RW)     // 24 threshold candidates
#define CAP  128            // compaction capacity

// Scratch between the two stages (no cudaMalloc allowed).
__device__ float g_w[N * K];
__device__ int   g_idx[N * K];

// Order-preserving float -> uint32 (bigger float => bigger uint).
__device__ __forceinline__ uint32_t f2ord(float f) {
    uint32_t u = __float_as_uint(f);
    return (u & 0x80000000u) ? ~u : (u | 0x80000000u);
}
__device__ __forceinline__ float ord2f(uint32_t u) {
    return __uint_as_float((u & 0x80000000u) ? (u & 0x7fffffffu) : ~u);
}

// ---------------------------------------------------------------------------
// Stage 1: softmax stats + exact top-20 via threshold filter + rank select.
// ---------------------------------------------------------------------------
__global__ __launch_bounds__(TPB) void topk_softmax_kernel(const float* __restrict__ M) {
    const int row  = blockIdx.x;
    const int tid  = threadIdx.x;
    const int lane = tid & 31;
    const int warp = tid >> 5;

    const float* r = M + (size_t)row * N + warp * WCOLS;
    float v[VPW];
#pragma unroll
    for (int j = 0; j < VPW; j++) v[j] = r[lane + j * 32];   // coalesced, MLP=16

    __shared__ uint32_t s_cval[NCAND];
    __shared__ float    s_mw[NW], s_sw[NW];
    __shared__ uint32_t s_t;
    __shared__ float    s_m, s_inv;
    __shared__ int      s_cnt;
    __shared__ uint64_t s_cand[CAP];

    // ---- per-warp max & sum of exp (rescaled later) ----
    float mw = v[0];
#pragma unroll
    for (int j = 1; j < VPW; j++) mw = fmaxf(mw, v[j]);
#pragma unroll
    for (int off = 16; off; off >>= 1) mw = fmaxf(mw, __shfl_xor_sync(0xffffffffu, mw, off));
    float sw = 0.f;
#pragma unroll
    for (int j = 0; j < VPW; j++) sw += __expf(v[j] - mw);
#pragma unroll
    for (int off = 16; off; off >>= 1) sw += __shfl_xor_sync(0xffffffffu, sw, off);
    if (lane == 0) { s_mw[warp] = mw; s_sw[warp] = sw; }

    // ---- ordered-u32 copy; 3 cheap value-only argmax rounds (REDUX) ----
    uint32_t u[VPW];
#pragma unroll
    for (int j = 0; j < VPW; j++) u[j] = f2ord(v[j]);
#pragma unroll
    for (int k = 0; k < RW; k++) {
        uint32_t w0 = u[0];
#pragma unroll
        for (int j = 1; j < VPW; j++) w0 = max(w0, u[j]);
        w0 = __reduce_max_sync(0xffffffffu, w0);
        if (lane == 0) s_cval[warp * RW + k] = w0;
#pragma unroll
        for (int j = 0; j < VPW; j++) if (u[j] == w0) u[j] = 0;
    }
    __syncthreads();

    // ---- warp 0: row stats + threshold (20th largest of 24 candidates) ----
    if (warp == 0) {
        float m = (lane < NW) ? s_mw[lane] : -FLT_MAX;
#pragma unroll
        for (int off = 4; off; off >>= 1) m = fmaxf(m, __shfl_xor_sync(0xffffffffu, m, off));
        float s = (lane < NW) ? s_sw[lane] * __expf(s_mw[lane] - m) : 0.f;
#pragma unroll
        for (int off = 4; off; off >>= 1) s += __shfl_xor_sync(0xffffffffu, s, off);

        uint32_t cv = (lane < NCAND) ? s_cval[lane] : 0u;
        int rk = 0;
#pragma unroll
        for (int q = 1; q < 32; q++) {
            int ol = (lane + q) & 31;
            uint32_t o = __shfl_sync(0xffffffffu, cv, ol);
            rk += (o > cv) || (o == cv && ol < lane);
        }
        if (rk == K - 1) s_t = cv;          // exactly one lane
        if (lane == 0) { s_m = m; s_inv = 1.0f / s; s_cnt = 0; }
    }
    __syncthreads();

    // ---- compact all values >= t (captures entire top-20 by construction) ----
    const uint32_t t = s_t;
#pragma unroll
    for (int j = 0; j < VPW; j++) {
        uint32_t uv = f2ord(v[j]);
        if (uv >= t) {
            int pos = atomicAdd(&s_cnt, 1);
            if (pos < CAP) {
                int col = warp * WCOLS + lane + j * 32;
                s_cand[pos] = ((uint64_t)uv << 32) | (uint32_t)(~col);
            }
        }
    }
    __syncthreads();

    // ---- warp 0: all-pairs rank over candidates; rank < 20 => output slot ----
    if (warp == 0) {
        const int   cnt = min(s_cnt, CAP);
        const float m   = s_m;
        const float inv = s_inv;

        if (cnt <= 64) {
            uint64_t c0 = (lane      < cnt) ? s_cand[lane]      : 0ull;
            uint64_t c1 = (lane + 32 < cnt) ? s_cand[lane + 32] : 0ull;
            int r0 = 0, r1 = 0;
            for (int q = 0; q < 32; q++) {
                uint64_t o0 = __shfl_sync(0xffffffffu, c0, q);
                uint64_t o1 = __shfl_sync(0xffffffffu, c1, q);
                r0 += (o0 > c0) + (o1 > c0);
                r1 += (o0 > c1) + (o1 > c1);
            }
            if (lane < cnt && r0 < K) {
                int ci = (int)(~(uint32_t)c0);
                g_idx[row * K + r0] = ci;
                g_w[row * K + r0]   = __expf(ord2f((uint32_t)(c0 >> 32)) - m) * inv;
            }
            if (lane + 32 < cnt && r1 < K) {
                int ci = (int)(~(uint32_t)c1);
                g_idx[row * K + r1] = ci;
                g_w[row * K + r1]   = __expf(ord2f((uint32_t)(c1 >> 32)) - m) * inv;
            }
        } else {
            uint64_t c0 = (lane      < cnt) ? s_cand[lane]      : 0ull;
            uint64_t c1 = (lane + 32 < cnt) ? s_cand[lane + 32] : 0ull;
            uint64_t c2 = (lane + 64 < cnt) ? s_cand[lane + 64] : 0ull;
            uint64_t c3 = (lane + 96 < cnt) ? s_cand[lane + 96] : 0ull;
            int r0 = 0, r1 = 0, r2 = 0, r3 = 0;
            for (int q = 0; q < 32; q++) {
                uint64_t o0 = __shfl_sync(0xffffffffu, c0, q);
                uint64_t o1 = __shfl_sync(0xffffffffu, c1, q);
                uint64_t o2 = __shfl_sync(0xffffffffu, c2, q);
                uint64_t o3 = __shfl_sync(0xffffffffu, c3, q);
                r0 += (o0 > c0) + (o1 > c0) + (o2 > c0) + (o3 > c0);
                r1 += (o0 > c1) + (o1 > c1) + (o2 > c1) + (o3 > c1);
                r2 += (o0 > c2) + (o1 > c2) + (o2 > c2) + (o3 > c2);
                r3 += (o0 > c3) + (o1 > c3) + (o2 > c3) + (o3 > c3);
            }
            if (lane < cnt && r0 < K) {
                g_idx[row * K + r0] = (int)(~(uint32_t)c0);
                g_w[row * K + r0]   = __expf(ord2f((uint32_t)(c0 >> 32)) - m) * inv;
            }
            if (lane + 32 < cnt && r1 < K) {
                g_idx[row * K + r1] = (int)(~(uint32_t)c1);
                g_w[row * K + r1]   = __expf(ord2f((uint32_t)(c1 >> 32)) - m) * inv;
            }
            if (lane + 64 < cnt && r2 < K) {
                g_idx[row * K + r2] = (int)(~(uint32_t)c2);
                g_w[row * K + r2]   = __expf(ord2f((uint32_t)(c2 >> 32)) - m) * inv;
            }
            if (lane + 96 < cnt && r3 < K) {
                g_idx[row * K + r3] = (int)(~(uint32_t)c3);
                g_w[row * K + r3]   = __expf(ord2f((uint32_t)(c3 >> 32)) - m) * inv;
            }
        }
    }
}

// ---------------------------------------------------------------------------
// Stage 2: out[b,i,:] = src1[b,i,:] + sum_k w[i,k] * src2[b, idx[i,k], :]
// One block per row i; 256 threads = (b in 0..3) x (64 float4 lanes of D=256).
// ---------------------------------------------------------------------------
__global__ __launch_bounds__(256) void gather_wsum_kernel(const float* __restrict__ src1,
                                                          const float* __restrict__ src2,
                                                          float* __restrict__ out) {
    const int i   = blockIdx.x;
    const int tid = threadIdx.x;
    const int b   = tid >> 6;    // 0..3
    const int d4  = tid & 63;    // float4 lane

    __shared__ float sw[K];
    __shared__ int   sj[K];
    if (tid < K) { sw[tid] = g_w[i * K + tid]; sj[tid] = g_idx[i * K + tid]; }
    __syncthreads();

    const size_t base = ((size_t)b * N + i) * D;
    float4 acc = ((const float4*)(src1 + base))[d4];
    const float4* s2 = (const float4*)(src2 + (size_t)b * N * D);

#pragma unroll
    for (int k = 0; k < K; k++) {
        const float  w = sw[k];
        const float4 x = s2[(size_t)sj[k] * (D / 4) + d4];
        acc.x = fmaf(w, x.x, acc.x);
        acc.y = fmaf(w, x.y, acc.y);
        acc.z = fmaf(w, x.z, acc.z);
        acc.w = fmaf(w, x.w, acc.w);
    }
    ((float4*)(out + base))[d4] = acc;
}

// ---------------------------------------------------------------------------
extern "C" void kernel_launch(void* const* d_in, const int* in_sizes, int n_in,
                              void* d_out, int out_size) {
    const float* src1 = (const float*)d_in[0];
    const float* src2 = (const float*)d_in[1];
    const float* M    = (const float*)d_in[2];
    float*       out  = (float*)d_out;

    topk_softmax_kernel<<<N, TPB>>>(M);
    gather_wsum_kernel<<<N, 256>>>(src1, src2, out);
}

// round 6
// speedup vs baseline: 4.6568x; 1.0868x over previous
#include <cuda_runtime.h>
#include <float.h>
#include <math.h>
#include <stdint.h>

#define N    4096
#define D    256
#define K    20
#define TPB  256
#define NW   8              // warps per block
#define WCOLS 512           // columns per warp
#define VPW  16             // values per thread (4 x float4)
#define RW   3              // per-warp candidate rounds
#define NCAND (NW * RW)     // 24 threshold candidates
#define CAP  128            // compaction capacity

// Order-preserving float -> uint32 (bigger float => bigger uint).
__device__ __forceinline__ uint32_t f2ord(float f) {
    uint32_t u = __float_as_uint(f);
    return (u & 0x80000000u) ? ~u : (u | 0x80000000u);
}
__device__ __forceinline__ float ord2f(uint32_t u) {
    return __uint_as_float((u & 0x80000000u) ? (u & 0x7fffffffu) : ~u);
}

// ---------------------------------------------------------------------------
// Fused: per-row softmax stats + exact top-20 (threshold filter + rank
// select) + weighted gather of src2 + residual. One block per row.
// ---------------------------------------------------------------------------
__global__ __launch_bounds__(TPB) void fused_kernel(const float* __restrict__ src1,
                                                    const float* __restrict__ src2,
                                                    const float* __restrict__ M,
                                                    float* __restrict__ out) {
    const int row  = blockIdx.x;
    const int tid  = threadIdx.x;
    const int lane = tid & 31;
    const int warp = tid >> 5;

    __shared__ uint32_t s_cval[NCAND];
    __shared__ float    s_mw[NW], s_sw[NW];
    __shared__ uint32_t s_t;
    __shared__ float    s_m, s_inv;
    __shared__ int      s_cnt;
    __shared__ uint64_t s_cand[CAP];
    __shared__ float    s_wk[K];
    __shared__ int      s_jk[K];

    // ================= Stage 1: softmax stats + top-20 =================
    {
        const float4* r4 = (const float4*)(M + (size_t)row * N + warp * WCOLS);
        float v[VPW];
#pragma unroll
        for (int j = 0; j < 4; j++) {
            float4 t4 = r4[lane + j * 32];          // LDG.128, coalesced
            v[j * 4 + 0] = t4.x; v[j * 4 + 1] = t4.y;
            v[j * 4 + 2] = t4.z; v[j * 4 + 3] = t4.w;
        }
        // column of v[j*4+c] = warp*WCOLS + 4*(lane + j*32) + c

        // per-warp max & sum of exp (rescaled later)
        float mw = v[0];
#pragma unroll
        for (int j = 1; j < VPW; j++) mw = fmaxf(mw, v[j]);
#pragma unroll
        for (int off = 16; off; off >>= 1) mw = fmaxf(mw, __shfl_xor_sync(0xffffffffu, mw, off));
        float sw = 0.f;
#pragma unroll
        for (int j = 0; j < VPW; j++) sw += __expf(v[j] - mw);
#pragma unroll
        for (int off = 16; off; off >>= 1) sw += __shfl_xor_sync(0xffffffffu, sw, off);
        if (lane == 0) { s_mw[warp] = mw; s_sw[warp] = sw; }

        // ordered copy; 3 value-only argmax rounds (REDUX)
        uint32_t u[VPW];
#pragma unroll
        for (int j = 0; j < VPW; j++) u[j] = f2ord(v[j]);
#pragma unroll
        for (int k = 0; k < RW; k++) {
            uint32_t w0 = u[0];
#pragma unroll
            for (int j = 1; j < VPW; j++) w0 = max(w0, u[j]);
            w0 = __reduce_max_sync(0xffffffffu, w0);
            if (lane == 0) s_cval[warp * RW + k] = w0;
#pragma unroll
            for (int j = 0; j < VPW; j++) if (u[j] == w0) u[j] = 0;
        }
        __syncthreads();

        // warp 0: row stats + threshold (20th largest of 24 candidates)
        if (warp == 0) {
            float m = (lane < NW) ? s_mw[lane] : -FLT_MAX;
#pragma unroll
            for (int off = 4; off; off >>= 1) m = fmaxf(m, __shfl_xor_sync(0xffffffffu, m, off));
            float s = (lane < NW) ? s_sw[lane] * __expf(s_mw[lane] - m) : 0.f;
#pragma unroll
            for (int off = 4; off; off >>= 1) s += __shfl_xor_sync(0xffffffffu, s, off);

            uint32_t cv = (lane < NCAND) ? s_cval[lane] : 0u;
            int rk = 0;
#pragma unroll
            for (int q = 1; q < 32; q++) {
                int ol = (lane + q) & 31;
                uint32_t o = __shfl_sync(0xffffffffu, cv, ol);
                rk += (o > cv) || (o == cv && ol < lane);
            }
            if (rk == K - 1) s_t = cv;              // exactly one lane
            if (lane == 0) { s_m = m; s_inv = 1.0f / s; s_cnt = 0; }
        }
        __syncthreads();

        // compact values >= t (provably contains the full top-20)
        const uint32_t t = s_t;
#pragma unroll
        for (int j = 0; j < VPW; j++) {
            uint32_t uv = f2ord(v[j]);
            if (uv >= t) {
                int pos = atomicAdd(&s_cnt, 1);
                if (pos < CAP) {
                    int col = warp * WCOLS + 4 * (lane + (j >> 2) * 32) + (j & 3);
                    s_cand[pos] = ((uint64_t)uv << 32) | (uint32_t)(~col);
                }
            }
        }
        __syncthreads();

        // warp 0: all-pairs rank over candidates; rank < 20 => output slot
        if (warp == 0) {
            const int   cnt = min(s_cnt, CAP);
            const float m   = s_m;
            const float inv = s_inv;

            uint64_t c0 = (lane      < cnt) ? s_cand[lane]      : 0ull;
            uint64_t c1 = (lane + 32 < cnt) ? s_cand[lane + 32] : 0ull;
            uint64_t c2 = (lane + 64 < cnt) ? s_cand[lane + 64] : 0ull;
            uint64_t c3 = (lane + 96 < cnt) ? s_cand[lane + 96] : 0ull;
            if (cnt <= 64) {
                int r0 = 0, r1 = 0;
                for (int q = 0; q < 32; q++) {
                    uint64_t o0 = __shfl_sync(0xffffffffu, c0, q);
                    uint64_t o1 = __shfl_sync(0xffffffffu, c1, q);
                    r0 += (o0 > c0) + (o1 > c0);
                    r1 += (o0 > c1) + (o1 > c1);
                }
                if (lane < cnt && r0 < K) {
                    s_jk[r0] = (int)(~(uint32_t)c0);
                    s_wk[r0] = __expf(ord2f((uint32_t)(c0 >> 32)) - m) * inv;
                }
                if (lane + 32 < cnt && r1 < K) {
                    s_jk[r1] = (int)(~(uint32_t)c1);
                    s_wk[r1] = __expf(ord2f((uint32_t)(c1 >> 32)) - m) * inv;
                }
            } else {
                int r0 = 0, r1 = 0, r2 = 0, r3 = 0;
                for (int q = 0; q < 32; q++) {
                    uint64_t o0 = __shfl_sync(0xffffffffu, c0, q);
                    uint64_t o1 = __shfl_sync(0xffffffffu, c1, q);
                    uint64_t o2 = __shfl_sync(0xffffffffu, c2, q);
                    uint64_t o3 = __shfl_sync(0xffffffffu, c3, q);
                    r0 += (o0 > c0) + (o1 > c0) + (o2 > c0) + (o3 > c0);
                    r1 += (o0 > c1) + (o1 > c1) + (o2 > c1) + (o3 > c1);
                    r2 += (o0 > c2) + (o1 > c2) + (o2 > c2) + (o3 > c2);
                    r3 += (o0 > c3) + (o1 > c3) + (o2 > c3) + (o3 > c3);
                }
                if (lane < cnt && r0 < K) {
                    s_jk[r0] = (int)(~(uint32_t)c0);
                    s_wk[r0] = __expf(ord2f((uint32_t)(c0 >> 32)) - m) * inv;
                }
                if (lane + 32 < cnt && r1 < K) {
                    s_jk[r1] = (int)(~(uint32_t)c1);
                    s_wk[r1] = __expf(ord2f((uint32_t)(c1 >> 32)) - m) * inv;
                }
                if (lane + 64 < cnt && r2 < K) {
                    s_jk[r2] = (int)(~(uint32_t)c2);
                    s_wk[r2] = __expf(ord2f((uint32_t)(c2 >> 32)) - m) * inv;
                }
                if (lane + 96 < cnt && r3 < K) {
                    s_jk[r3] = (int)(~(uint32_t)c3);
                    s_wk[r3] = __expf(ord2f((uint32_t)(c3 >> 32)) - m) * inv;
                }
            }
        }
        __syncthreads();
    }

    // ================= Stage 2: weighted gather + residual =================
    {
        const int b  = tid >> 6;    // 0..3
        const int d4 = tid & 63;    // float4 lane of D=256

        const size_t base = ((size_t)b * N + row) * D;
        const float4* s2  = (const float4*)(src2 + (size_t)b * N * D) + d4;

        float4 a0 = ((const float4*)(src1 + base))[d4];
        float4 a1 = make_float4(0.f, 0.f, 0.f, 0.f);

        // 4 groups of 5: explicit load batches (MLP ~5+) feeding split accums
#pragma unroll
        for (int g = 0; g < 4; g++) {
            float  wv[5];
            float4 x[5];
#pragma unroll
            for (int j = 0; j < 5; j++) {
                const int kk = g * 5 + j;
                wv[j] = s_wk[kk];
                x[j]  = s2[(size_t)s_jk[kk] * (D / 4)];
            }
#pragma unroll
            for (int j = 0; j < 5; j++) {
                float4& acc = (j & 1) ? a1 : a0;
                acc.x = fmaf(wv[j], x[j].x, acc.x);
                acc.y = fmaf(wv[j], x[j].y, acc.y);
                acc.z = fmaf(wv[j], x[j].z, acc.z);
                acc.w = fmaf(wv[j], x[j].w, acc.w);
            }
        }
        a0.x += a1.x; a0.y += a1.y; a0.z += a1.z; a0.w += a1.w;
        ((float4*)(out + base))[d4] = a0;
    }
}

// ---------------------------------------------------------------------------
extern "C" void kernel_launch(void* const* d_in, const int* in_sizes, int n_in,
                              void* d_out, int out_size) {
    const float* src1 = (const float*)d_in[0];
    const float* src2 = (const float*)d_in[1];
    const float* M    = (const float*)d_in[2];
    float*       out  = (float*)d_out;

    fused_kernel<<<N, TPB>>>(src1, src2, M, out);
}